// round 1
// baseline (speedup 1.0000x reference)
#include <cuda_runtime.h>
#include <cstdint>

// CSpace resonator bank: each channel is a 1st-order complex IIR.
// y[t] = eig*y[t-1] + g*x[t]   (forward),  y[t] = eig*y[t+1] + g*x[t] (backward)
// with g = kernels[c,0], eig = kernels[c,1]/kernels[c,0].
// Output (B=8, 4*C=256, T=48000) float32: [ReF, ImF, ReB, ImB] channel planes.

#define TT 48000
#define CC 64
#define BB 8
#define KLEN 24000

// One warp owns one (b, c, dir) sequence. Per 128-sample iteration:
// blocked affine scan across the 32 lanes (4 serial samples per lane).
template <bool REV>
__device__ __forceinline__ void run_seq(const float* __restrict__ x,
                                        float* __restrict__ out_re,
                                        float* __restrict__ out_im,
                                        double der, double dei,
                                        float gr, float gi)
{
    const int lane = threadIdx.x & 31;
    const unsigned FULL = 0xFFFFFFFFu;

    // ---- constants in double, cast to float (keeps long-lag phase accurate) ----
    // E4 = eig^4
    double e2r = der * der - dei * dei, e2i = 2.0 * der * dei;
    double e4r = e2r * e2r - e2i * e2i, e4i = 2.0 * e2r * e2i;
    // scan coefficients A_k = E4^(2^k), k = 0..4 ; Afin = E4^32 = eig^128
    double pr_[6], pi_[6];
    pr_[0] = e4r; pi_[0] = e4i;
    #pragma unroll
    for (int k = 1; k < 6; ++k) {
        pr_[k] = pr_[k-1]*pr_[k-1] - pi_[k-1]*pi_[k-1];
        pi_[k] = 2.0 * pr_[k-1] * pi_[k-1];
    }
    const float a0r=(float)pr_[0], a0i=(float)pi_[0];
    const float a1r=(float)pr_[1], a1i=(float)pi_[1];
    const float a2r=(float)pr_[2], a2i=(float)pi_[2];
    const float a3r=(float)pr_[3], a3i=(float)pi_[3];
    const float a4r=(float)pr_[4], a4i=(float)pi_[4];
    const float afr=(float)pr_[5], afi=(float)pi_[5];
    // Q = E4^lane (state propagation into this lane)
    double dqr = 1.0, dqi = 0.0;
    for (int j = 0; j < 31; ++j) {
        if (lane > j) {
            double tr = dqr * e4r - dqi * e4i;
            double ti = dqr * e4i + dqi * e4r;
            dqr = tr; dqi = ti;
        }
    }
    const float qr = (float)dqr, qi = (float)dqi;
    const float er = (float)der,  ei = (float)dei;

    float pr = 0.f, pi = 0.f;   // carried state y[-1]

    // depth-2 load pipeline (hide L2 latency; only ~2 warps/SMSP)
    auto load4 = [&](int it) -> float4 {
        int sbase = it * 128 + lane * 4;
        if (!REV) return *reinterpret_cast<const float4*>(x + sbase);
        else      return *reinterpret_cast<const float4*>(x + (TT - 4 - sbase));
    };
    const int NIT = TT / 128;  // 375, exact
    float4 buf0 = load4(0);
    float4 buf1 = load4(1 < NIT ? 1 : 0);

    for (int it = 0; it < NIT; ++it) {
        float4 X = buf0;
        buf0 = buf1;
        int nx = it + 2; if (nx > NIT - 1) nx = NIT - 1;
        buf1 = load4(nx);

        float x0, x1, x2, x3;
        if (!REV) { x0 = X.x; x1 = X.y; x2 = X.z; x3 = X.w; }
        else      { x0 = X.w; x1 = X.z; x2 = X.y; x3 = X.x; }

        // local affine term over 4 samples from zero state
        float cr = gr * x0, ci = gi * x0;
        float tr, ti;
        tr = er*cr - ei*ci + gr*x1; ti = er*ci + ei*cr + gi*x1; cr = tr; ci = ti;
        tr = er*cr - ei*ci + gr*x2; ti = er*ci + ei*cr + gi*x2; cr = tr; ci = ti;
        tr = er*cr - ei*ci + gr*x3; ti = er*ci + ei*cr + gi*x3; cr = tr; ci = ti;

        // inclusive Kogge-Stone scan: S_l = c_l + E4 * S_{l-1}
        float sr = cr, si = ci;
        { float ur = __shfl_up_sync(FULL, sr, 1),  ui = __shfl_up_sync(FULL, si, 1);
          if (lane >= 1)  { sr += a0r*ur - a0i*ui; si += a0r*ui + a0i*ur; } }
        { float ur = __shfl_up_sync(FULL, sr, 2),  ui = __shfl_up_sync(FULL, si, 2);
          if (lane >= 2)  { sr += a1r*ur - a1i*ui; si += a1r*ui + a1i*ur; } }
        { float ur = __shfl_up_sync(FULL, sr, 4),  ui = __shfl_up_sync(FULL, si, 4);
          if (lane >= 4)  { sr += a2r*ur - a2i*ui; si += a2r*ui + a2i*ur; } }
        { float ur = __shfl_up_sync(FULL, sr, 8),  ui = __shfl_up_sync(FULL, si, 8);
          if (lane >= 8)  { sr += a3r*ur - a3i*ui; si += a3r*ui + a3i*ur; } }
        { float ur = __shfl_up_sync(FULL, sr, 16), ui = __shfl_up_sync(FULL, si, 16);
          if (lane >= 16) { sr += a4r*ur - a4i*ui; si += a4r*ui + a4i*ur; } }

        // incoming state for this lane: y = S_{l-1} + E4^l * p
        float hr = __shfl_up_sync(FULL, sr, 1);
        float hi = __shfl_up_sync(FULL, si, 1);
        if (lane == 0) { hr = 0.f; hi = 0.f; }
        float yr = hr + qr*pr - qi*pi;
        float yi = hi + qr*pi + qi*pr;

        // replay 4 steps producing outputs
        float o0r,o0i,o1r,o1i,o2r,o2i,o3r,o3i;
        tr = er*yr - ei*yi + gr*x0; ti = er*yi + ei*yr + gi*x0; yr=tr; yi=ti; o0r=yr; o0i=yi;
        tr = er*yr - ei*yi + gr*x1; ti = er*yi + ei*yr + gi*x1; yr=tr; yi=ti; o1r=yr; o1i=yi;
        tr = er*yr - ei*yi + gr*x2; ti = er*yi + ei*yr + gi*x2; yr=tr; yi=ti; o2r=yr; o2i=yi;
        tr = er*yr - ei*yi + gr*x3; ti = er*yi + ei*yr + gi*x3; yr=tr; yi=ti; o3r=yr; o3i=yi;

        int sbase = it * 128 + lane * 4;
        if (!REV) {
            *reinterpret_cast<float4*>(out_re + sbase) = make_float4(o0r, o1r, o2r, o3r);
            *reinterpret_cast<float4*>(out_im + sbase) = make_float4(o0i, o1i, o2i, o3i);
        } else {
            *reinterpret_cast<float4*>(out_re + (TT - 4 - sbase)) = make_float4(o3r, o2r, o1r, o0r);
            *reinterpret_cast<float4*>(out_im + (TT - 4 - sbase)) = make_float4(o3i, o2i, o1i, o0i);
        }

        // advance carried state: p = S_31 + eig^128 * p
        float b31r = __shfl_sync(FULL, sr, 31);
        float b31i = __shfl_sync(FULL, si, 31);
        tr = b31r + afr*pr - afi*pi;
        ti = b31i + afr*pi + afi*pr;
        pr = tr; pi = ti;
    }
}

__global__ void __launch_bounds__(32)
cspace_iir_kernel(const float* __restrict__ audio,
                  const float* __restrict__ kre,
                  const float* __restrict__ kim,
                  float* __restrict__ out)
{
    // warp id = blockIdx.x in [0, 1024): dir = bit0, c = bits[1:7), b = bits[7:10)
    int w   = blockIdx.x;
    int dir = w & 1;
    int c   = (w >> 1) & 63;
    int b   = w >> 7;

    // derive eig, g from the first two kernel samples (kernel[c,k] = eig^k / norm)
    float k0r = kre[c * KLEN + 0], k0i = kim[c * KLEN + 0];
    float k1r = kre[c * KLEN + 1], k1i = kim[c * KLEN + 1];
    double inv = 1.0 / ((double)k0r * k0r + (double)k0i * k0i);
    double der = ((double)k1r * k0r + (double)k1i * k0i) * inv;
    double dei = ((double)k1i * k0r - (double)k1r * k0i) * inv;
    float gr = k0r, gi = k0i;

    const float* x = audio + (size_t)b * TT;
    float* base = out + (size_t)b * 4 * CC * TT;

    if (dir == 0) {
        run_seq<false>(x, base + (size_t)c * TT,
                          base + (size_t)(CC + c) * TT, der, dei, gr, gi);
    } else {
        run_seq<true>(x,  base + (size_t)(2 * CC + c) * TT,
                          base + (size_t)(3 * CC + c) * TT, der, dei, gr, gi);
    }
}

extern "C" void kernel_launch(void* const* d_in, const int* in_sizes, int n_in,
                              void* d_out, int out_size)
{
    const float* audio = (const float*)d_in[0];
    const float* kre   = (const float*)d_in[1];
    const float* kim   = (const float*)d_in[2];
    float* out = (float*)d_out;
    (void)in_sizes; (void)n_in; (void)out_size;

    cspace_iir_kernel<<<BB * CC * 2, 32>>>(audio, kre, kim, out);
}

// round 2
// speedup vs baseline: 1.4357x; 1.4357x over previous
#include <cuda_runtime.h>
#include <cstdint>

// CSpace resonator bank as 1st-order complex IIR, block-parallel affine scan.
// One block (15 warps, 480 thr) per (b, c, dir) sequence; 1920 samples/iter.

#define TT 48000
#define CC 64
#define BB 8
#define KLEN 24000
#define NWARPS 15
#define NTHREADS 480
#define NIT 25          // 25 * 1920 = 48000 exact

__device__ __forceinline__ void cmulD(double& ar, double& ai, double br, double bi) {
    double tr = ar * br - ai * bi;
    ai = ar * bi + ai * br;
    ar = tr;
}

template <bool REV>
__device__ __forceinline__ void run_seq(const float* __restrict__ x,
                                        float* __restrict__ out_re,
                                        float* __restrict__ out_im,
                                        double der, double dei,
                                        float gr, float gi,
                                        float2* __restrict__ s_tot)
{
    const int tid  = threadIdx.x;
    const int lane = tid & 31;
    const int w    = tid >> 5;
    const unsigned FULL = 0xFFFFFFFFu;

    // ---- double-precision power tables ----
    // A[k] = E4^(2^k), k=0..8  (A[5] = E128, ..., A[8] = E1024)
    double E2r = der*der - dei*dei, E2i = 2.0*der*dei;
    double E3r = E2r, E3i = E2i; cmulD(E3r, E3i, der, dei);
    double E4r = E2r, E4i = E2i; cmulD(E4r, E4i, E2r, E2i);
    double Ar[9], Ai[9];
    Ar[0] = E4r; Ai[0] = E4i;
    #pragma unroll
    for (int k = 1; k < 9; ++k) {
        Ar[k] = Ar[k-1]; Ai[k] = Ai[k-1];
        cmulD(Ar[k], Ai[k], Ar[k-1], Ai[k-1]);   // square
    }
    // q = E4^lane  (binary exponentiation over A[0..4])
    double qdr = 1.0, qdi = 0.0;
    #pragma unroll
    for (int k = 0; k < 5; ++k) if ((lane >> k) & 1) cmulD(qdr, qdi, Ar[k], Ai[k]);
    // W = E128^w   (binary exponentiation over A[5..8])
    double wdr = 1.0, wdi = 0.0;
    #pragma unroll
    for (int k = 0; k < 4; ++k) if ((w >> k) & 1) cmulD(wdr, wdi, Ar[5+k], Ai[5+k]);
    // F = E1920 = E128^15 = A5*A6*A7*A8
    double fdr = Ar[5], fdi = Ai[5];
    cmulD(fdr, fdi, Ar[6], Ai[6]);
    cmulD(fdr, fdi, Ar[7], Ai[7]);
    cmulD(fdr, fdi, Ar[8], Ai[8]);

    const float e1r=(float)der, e1i=(float)dei;
    const float e2r=(float)E2r, e2i=(float)E2i;
    const float e3r=(float)E3r, e3i=(float)E3i;
    const float e4r=(float)E4r, e4i=(float)E4i;
    const float a0r=(float)Ar[0], a0i=(float)Ai[0];
    const float a1r=(float)Ar[1], a1i=(float)Ai[1];
    const float a2r=(float)Ar[2], a2i=(float)Ai[2];
    const float a3r=(float)Ar[3], a3i=(float)Ai[3];
    const float a4r=(float)Ar[4], a4i=(float)Ai[4];
    const float b0r=(float)Ar[5], b0i=(float)Ai[5];
    const float b1r=(float)Ar[6], b1i=(float)Ai[6];
    const float b2r=(float)Ar[7], b2i=(float)Ai[7];
    const float b3r=(float)Ar[8], b3i=(float)Ai[8];
    const float qr=(float)qdr, qi=(float)qdi;
    const float Wr=(float)wdr, Wi=(float)wdi;
    const float Fr=(float)fdr, Fi=(float)fdi;

    float pr = 0.f, pi = 0.f;   // carried block-entry state y[-1]

    auto load4 = [&](int it) -> float4 {
        int sbase = it * (NTHREADS * 4) + tid * 4;
        if (!REV) return *reinterpret_cast<const float4*>(x + sbase);
        else      return *reinterpret_cast<const float4*>(x + (TT - 4 - sbase));
    };

    float4 buf = load4(0);

    for (int it = 0; it < NIT; ++it) {
        float4 X = buf;
        if (it + 1 < NIT) buf = load4(it + 1);

        float x0, x1, x2, x3;
        if (!REV) { x0 = X.x; x1 = X.y; x2 = X.z; x3 = X.w; }
        else      { x0 = X.w; x1 = X.z; x2 = X.y; x3 = X.x; }

        // local partial states from zero init (kept for output reconstruction)
        float c1r = gr*x0, c1i = gi*x0;
        float c2r = e1r*c1r - e1i*c1i + gr*x1, c2i = e1r*c1i + e1i*c1r + gi*x1;
        float c3r = e1r*c2r - e1i*c2i + gr*x2, c3i = e1r*c2i + e1i*c2r + gi*x2;
        float c4r = e1r*c3r - e1i*c3i + gr*x3, c4i = e1r*c3i + e1i*c3r + gi*x3;

        // warp-level inclusive Kogge-Stone scan: S_l = C_l + E4 * S_{l-1}
        float sr = c4r, si = c4i;
        { float ur=__shfl_up_sync(FULL,sr,1),  ui=__shfl_up_sync(FULL,si,1);
          if (lane>=1)  { sr += a0r*ur - a0i*ui; si += a0r*ui + a0i*ur; } }
        { float ur=__shfl_up_sync(FULL,sr,2),  ui=__shfl_up_sync(FULL,si,2);
          if (lane>=2)  { sr += a1r*ur - a1i*ui; si += a1r*ui + a1i*ur; } }
        { float ur=__shfl_up_sync(FULL,sr,4),  ui=__shfl_up_sync(FULL,si,4);
          if (lane>=4)  { sr += a2r*ur - a2i*ui; si += a2r*ui + a2i*ur; } }
        { float ur=__shfl_up_sync(FULL,sr,8),  ui=__shfl_up_sync(FULL,si,8);
          if (lane>=8)  { sr += a3r*ur - a3i*ui; si += a3r*ui + a3i*ur; } }
        { float ur=__shfl_up_sync(FULL,sr,16), ui=__shfl_up_sync(FULL,si,16);
          if (lane>=16) { sr += a4r*ur - a4i*ui; si += a4r*ui + a4i*ur; } }

        // exclusive lane prefix (independent of cross-warp work)
        float hr = __shfl_up_sync(FULL, sr, 1);
        float hi = __shfl_up_sync(FULL, si, 1);
        if (lane == 0) { hr = 0.f; hi = 0.f; }

        // publish warp totals (double-buffered -> single barrier per iter)
        float2* tot = s_tot + (it & 1) * 16;
        if (lane == 31) tot[w] = make_float2(sr, si);
        __syncthreads();

        // every warp redundantly scans the 15 warp totals:
        // S_w = C_w + E128 * S_{w-1}
        float2 tv = (lane < NWARPS) ? tot[lane] : make_float2(0.f, 0.f);
        float tr_ = tv.x, ti_ = tv.y;
        { float ur=__shfl_up_sync(FULL,tr_,1), ui=__shfl_up_sync(FULL,ti_,1);
          if (lane>=1) { tr_ += b0r*ur - b0i*ui; ti_ += b0r*ui + b0i*ur; } }
        { float ur=__shfl_up_sync(FULL,tr_,2), ui=__shfl_up_sync(FULL,ti_,2);
          if (lane>=2) { tr_ += b1r*ur - b1i*ui; ti_ += b1r*ui + b1i*ur; } }
        { float ur=__shfl_up_sync(FULL,tr_,4), ui=__shfl_up_sync(FULL,ti_,4);
          if (lane>=4) { tr_ += b2r*ur - b2i*ui; ti_ += b2r*ui + b2i*ur; } }
        { float ur=__shfl_up_sync(FULL,tr_,8), ui=__shfl_up_sync(FULL,ti_,8);
          if (lane>=8) { tr_ += b3r*ur - b3i*ui; ti_ += b3r*ui + b3i*ur; } }

        float exr = 0.f, exi = 0.f;
        if (w > 0) {
            exr = __shfl_sync(FULL, tr_, w - 1);
            exi = __shfl_sync(FULL, ti_, w - 1);
        }
        float totr = __shfl_sync(FULL, tr_, NWARPS - 1);
        float toti = __shfl_sync(FULL, ti_, NWARPS - 1);

        // warp-entry state: in = W * p + ex
        float inr = Wr*pr - Wi*pi + exr;
        float ini = Wr*pi + Wi*pr + exi;
        // lane-entry state: y = q * in + S_{l-1}
        float yr = qr*inr - qi*ini + hr;
        float yi = qr*ini + qi*inr + hi;

        // outputs: o_j = c_j + e^j * y  (independent complex FMAs)
        float o1r = c1r + e1r*yr - e1i*yi, o1i = c1i + e1r*yi + e1i*yr;
        float o2r = c2r + e2r*yr - e2i*yi, o2i = c2i + e2r*yi + e2i*yr;
        float o3r = c3r + e3r*yr - e3i*yi, o3i = c3i + e3r*yi + e3i*yr;
        float o4r = c4r + e4r*yr - e4i*yi, o4i = c4i + e4r*yi + e4i*yr;

        int sbase = it * (NTHREADS * 4) + tid * 4;
        if (!REV) {
            *reinterpret_cast<float4*>(out_re + sbase) = make_float4(o1r, o2r, o3r, o4r);
            *reinterpret_cast<float4*>(out_im + sbase) = make_float4(o1i, o2i, o3i, o4i);
        } else {
            *reinterpret_cast<float4*>(out_re + (TT - 4 - sbase)) = make_float4(o4r, o3r, o2r, o1r);
            *reinterpret_cast<float4*>(out_im + (TT - 4 - sbase)) = make_float4(o4i, o3i, o2i, o1i);
        }

        // advance carried state: p = E1920 * p + blockTotal
        float npr = Fr*pr - Fi*pi + totr;
        float npi = Fr*pi + Fi*pr + toti;
        pr = npr; pi = npi;
    }
}

__global__ void __launch_bounds__(NTHREADS, 2)
cspace_iir_kernel(const float* __restrict__ audio,
                  const float* __restrict__ kre,
                  const float* __restrict__ kim,
                  float* __restrict__ out)
{
    __shared__ float2 s_tot[32];   // double-buffered 15-warp totals

    int blk = blockIdx.x;          // [0, 1024)
    int dir = blk & 1;
    int c   = (blk >> 1) & 63;
    int b   = blk >> 7;

    // derive eig, g from the first two kernel samples (kernel[c,k] = eig^k / norm)
    float k0r = kre[c * KLEN + 0], k0i = kim[c * KLEN + 0];
    float k1r = kre[c * KLEN + 1], k1i = kim[c * KLEN + 1];
    double inv = 1.0 / ((double)k0r * k0r + (double)k0i * k0i);
    double der = ((double)k1r * k0r + (double)k1i * k0i) * inv;
    double dei = ((double)k1i * k0r - (double)k1r * k0i) * inv;
    float gr = k0r, gi = k0i;

    const float* x = audio + (size_t)b * TT;
    float* base = out + (size_t)b * 4 * CC * TT;

    if (dir == 0) {
        run_seq<false>(x, base + (size_t)c * TT,
                          base + (size_t)(CC + c) * TT, der, dei, gr, gi, s_tot);
    } else {
        run_seq<true>(x,  base + (size_t)(2 * CC + c) * TT,
                          base + (size_t)(3 * CC + c) * TT, der, dei, gr, gi, s_tot);
    }
}

extern "C" void kernel_launch(void* const* d_in, const int* in_sizes, int n_in,
                              void* d_out, int out_size)
{
    const float* audio = (const float*)d_in[0];
    const float* kre   = (const float*)d_in[1];
    const float* kim   = (const float*)d_in[2];
    float* out = (float*)d_out;
    (void)in_sizes; (void)n_in; (void)out_size;

    cspace_iir_kernel<<<BB * CC * 2, NTHREADS>>>(audio, kre, kim, out);
}